// round 1
// baseline (speedup 1.0000x reference)
#include <cuda_runtime.h>
#include <math.h>

// Problem constants
#define Bz   64
#define Tz   1024
#define Dz   128
#define Hz   512
#define Gz   2048          // 4*H
#define BT   65536         // B*T

// ---------------- scratch (device globals; no cudaMalloc allowed) ----------
__device__ float    g_xg[(size_t)Tz * Bz * Gz];     // [T][B][4H]  512 MB (reused both layers)
__device__ float    g_h1[(size_t)BT * Hz];          // [B][T][H]
__device__ float    g_h2[(size_t)BT * Hz];          // [B][T][H]
__device__ float    g_hping[2][Bz * Hz];            // recurrent h double buffer
__device__ unsigned g_bar;                          // grid barrier counter
__device__ float    g_ps [64 * Hz];                 // BN partial sums
__device__ float    g_ps2[64 * Hz];
__device__ float    g_bnA[Hz];                      // folded BN scale
__device__ float    g_bnB[Hz];                      // folded BN bias

// ---------------------------------------------------------------------------
// SGEMM: out[t][b][:] = A[m=b*T+t][:K] @ W[K][2048] + bias   (scatter to [T][B][G])
// BM=BN=128, BK=8, TM=TN=8, 256 threads
// ---------------------------------------------------------------------------
__global__ __launch_bounds__(256) void sgemm_xg(
    const float* __restrict__ A, const float* __restrict__ W,
    const float* __restrict__ bias, float* __restrict__ out, int K)
{
    __shared__ float As[8 * 128];
    __shared__ float Bs[8 * 128];

    const int tid  = threadIdx.x;
    const int cCol = blockIdx.x;   // 0..15
    const int cRow = blockIdx.y;   // 0..511

    const float* Ap = A + (size_t)cRow * 128 * K;
    const float* Wp = W + cCol * 128;

    const int innerRowA = tid >> 1;          // 0..127
    const int innerColA = tid & 1;           // 0..1 (x4 floats)
    const int innerRowB = tid >> 5;          // 0..7
    const int innerColB = tid & 31;          // 0..31 (x4 floats)
    const int threadRow = tid >> 4;          // 0..15
    const int threadCol = tid & 15;          // 0..15

    float acc[8][8];
#pragma unroll
    for (int i = 0; i < 8; i++)
#pragma unroll
        for (int j = 0; j < 8; j++) acc[i][j] = 0.f;

    float regM[8], regN[8];

    for (int k0 = 0; k0 < K; k0 += 8) {
        float4 ta = *reinterpret_cast<const float4*>(&Ap[innerRowA * K + k0 + innerColA * 4]);
        As[(innerColA * 4 + 0) * 128 + innerRowA] = ta.x;
        As[(innerColA * 4 + 1) * 128 + innerRowA] = ta.y;
        As[(innerColA * 4 + 2) * 128 + innerRowA] = ta.z;
        As[(innerColA * 4 + 3) * 128 + innerRowA] = ta.w;
        float4 tb = *reinterpret_cast<const float4*>(&Wp[(size_t)(k0 + innerRowB) * Gz + innerColB * 4]);
        *reinterpret_cast<float4*>(&Bs[innerRowB * 128 + innerColB * 4]) = tb;
        __syncthreads();

#pragma unroll
        for (int d = 0; d < 8; d++) {
#pragma unroll
            for (int i = 0; i < 8; i++) regM[i] = As[d * 128 + threadRow * 8 + i];
#pragma unroll
            for (int j = 0; j < 8; j++) regN[j] = Bs[d * 128 + threadCol * 8 + j];
#pragma unroll
            for (int i = 0; i < 8; i++)
#pragma unroll
                for (int j = 0; j < 8; j++) acc[i][j] += regM[i] * regN[j];
        }
        __syncthreads();
    }

    const int col0 = cCol * 128 + threadCol * 8;
#pragma unroll
    for (int i = 0; i < 8; i++) {
        int m  = cRow * 128 + threadRow * 8 + i;
        int bb = m >> 10;          // batch
        int tt = m & 1023;         // time
        float* orow = &out[(size_t)((tt << 6) + bb) << 11];  // *(64) then *2048
#pragma unroll
        for (int j = 0; j < 8; j += 4) {
            float4 bv = *reinterpret_cast<const float4*>(&bias[col0 + j]);
            float4 r;
            r.x = acc[i][j + 0] + bv.x;
            r.y = acc[i][j + 1] + bv.y;
            r.z = acc[i][j + 2] + bv.z;
            r.w = acc[i][j + 3] + bv.w;
            *reinterpret_cast<float4*>(&orow[col0 + j]) = r;
        }
    }
}

// ---------------------------------------------------------------------------
// reset: zero h ping buffer 0 + barrier counter (run before each recurrence)
// ---------------------------------------------------------------------------
__global__ void reset_state()
{
    int i = blockIdx.x * 512 + threadIdx.x;   // grid 64 x 512 = 32768 = B*H
    g_hping[0][i] = 0.f;
    if (i == 0) g_bar = 0u;
}

// ---------------------------------------------------------------------------
// Persistent LSTM recurrence.
// 128 CTAs x 256 threads, 1 CTA/SM (200KB smem) -> all resident, spin barrier ok.
// CTA owns 4 hidden units => 16 gate columns of Wh (stored gate-major: c = gate*4+unit).
// Per step: stage h [k][b] into smem (pad 68), tile-dot (4b x 8c x 8 k-splits),
// k-split reduce in smem, gate math + c update, write h, grid barrier.
// ---------------------------------------------------------------------------
#define SH_STRIDE 68
#define REC_SMEM  ((512 * SH_STRIDE + 512 * 16 + 8 * 1024) * 4)   // 204800 B

__device__ __forceinline__ float sigmoidf_(float x) { return 1.f / (1.f + expf(-x)); }

__global__ __launch_bounds__(256) void lstm_rec(
    const float* __restrict__ Wh,    // [512][2048]
    const float* __restrict__ xgp,   // [T][B][2048]
    float* __restrict__ hout)        // [B][T][512]
{
    extern __shared__ float sm[];
    float* sH = sm;                       // [512][68]
    float* sW = sm + 512 * SH_STRIDE;     // [512][16]
    float* sR = sW + 512 * 16;            // [8][16][64]

    const int tid = threadIdx.x;
    const int u0  = blockIdx.x * 4;

    // load this CTA's Wh slice, gate-major columns
    for (int i = tid; i < 512 * 16; i += 256) {
        int k = i >> 4, c = i & 15;
        int gate = c >> 2, un = c & 3;
        sW[i] = Wh[(size_t)k * Gz + gate * Hz + u0 + un];
    }

    // dot-role indices
    const int ks = tid >> 5;              // 0..7 (k split, one per warp)
    const int rem = tid & 31;
    const int c2 = rem >> 4;              // 0..1 (8 cols each)
    const int b4 = rem & 15;              // 0..15 (4 batches each)
    // stage-role indices
    const int sb = tid >> 2;              // 0..63 batch
    const int sq = tid & 3;               // 0..3
    // finalize-role indices
    const int fb = tid & 63;              // batch
    const int fu = tid >> 6;              // unit 0..3

    float creg = 0.f;
    __syncthreads();

    for (int t = 0; t < Tz; t++) {
        // ---- stage h_prev: global [b][k] -> smem [k][b], L1-bypass reads ----
        const float* hp = &g_hping[t & 1][0];
#pragma unroll 8
        for (int i2 = 0; i2 < 32; i2++) {
            int k4 = i2 * 4 + sq;                  // 0..127
            float4 v = __ldcg(reinterpret_cast<const float4*>(&hp[sb * 512 + (k4 << 2)]));
            int kb = k4 << 2;
            sH[(kb + 0) * SH_STRIDE + sb] = v.x;
            sH[(kb + 1) * SH_STRIDE + sb] = v.y;
            sH[(kb + 2) * SH_STRIDE + sb] = v.z;
            sH[(kb + 3) * SH_STRIDE + sb] = v.w;
        }
        __syncthreads();

        // ---- dot: acc[4 batches][8 cols] over this warp's 64 k values ----
        float acc[4][8];
#pragma unroll
        for (int i = 0; i < 4; i++)
#pragma unroll
            for (int j = 0; j < 8; j++) acc[i][j] = 0.f;

        const int kbase = ks * 64;
#pragma unroll 8
        for (int kk = 0; kk < 64; kk++) {
            int k = kbase + kk;
            float4 hv = *reinterpret_cast<const float4*>(&sH[k * SH_STRIDE + (b4 << 2)]);
            float4 w0 = *reinterpret_cast<const float4*>(&sW[(k << 4) + c2 * 8]);
            float4 w1 = *reinterpret_cast<const float4*>(&sW[(k << 4) + c2 * 8 + 4]);
            float hr[4] = {hv.x, hv.y, hv.z, hv.w};
            float wr[8] = {w0.x, w0.y, w0.z, w0.w, w1.x, w1.y, w1.z, w1.w};
#pragma unroll
            for (int i = 0; i < 4; i++)
#pragma unroll
                for (int j = 0; j < 8; j++) acc[i][j] += hr[i] * wr[j];
        }

        // ---- write k-split partials ----
#pragma unroll
        for (int i = 0; i < 4; i++)
#pragma unroll
            for (int j = 0; j < 8; j++)
                sR[(ks << 10) + ((c2 * 8 + j) << 6) + (b4 << 2) + i] = acc[i][j];
        __syncthreads();

        // ---- finalize: reduce splits, add xg, gate math, write h ----
        float gv[4];
#pragma unroll
        for (int g = 0; g < 4; g++) {
            int c = (g << 2) + fu;
            float s = 0.f;
#pragma unroll
            for (int kq = 0; kq < 8; kq++) s += sR[(kq << 10) + (c << 6) + fb];
            gv[g] = s + xgp[(size_t)((t << 6) + fb) * Gz + (g << 9) + u0 + fu];
        }
        float ig = sigmoidf_(gv[0]);
        float fg = sigmoidf_(gv[1]);
        float gg = tanhf(gv[2]);
        float og = sigmoidf_(gv[3]);
        creg = fg * creg + ig * gg;
        float hv = og * tanhf(creg);

        g_hping[(t & 1) ^ 1][fb * 512 + u0 + fu] = hv;
        hout[(size_t)((fb << 10) + t) * Hz + u0 + fu] = hv;

        // ---- grid barrier ----
        __threadfence();
        __syncthreads();
        if (tid == 0) {
            atomicAdd(&g_bar, 1u);
            unsigned tgt = (unsigned)(t + 1) * gridDim.x;
            volatile unsigned* vb = &g_bar;
            while (*vb < tgt) {}
        }
        __syncthreads();
    }
}

// ---------------------------------------------------------------------------
// BatchNorm (deterministic two-stage) + apply + head
// ---------------------------------------------------------------------------
__global__ void bn_partial(const float* __restrict__ h)
{
    int f = blockIdx.x * 128 + threadIdx.x;   // grid.x = 4
    int chunk = blockIdx.y;                    // grid.y = 64 (1024 rows each)
    const float* p = h + (size_t)chunk * 1024 * Hz + f;
    float s = 0.f, s2 = 0.f;
    for (int r = 0; r < 1024; r++) {
        float v = p[(size_t)r * Hz];
        s += v; s2 += v * v;
    }
    g_ps [chunk * Hz + f] = s;
    g_ps2[chunk * Hz + f] = s2;
}

__global__ void bn_finalize(const float* __restrict__ scale, const float* __restrict__ bias)
{
    int f = blockIdx.x * 128 + threadIdx.x;   // grid 4 x 128
    float s = 0.f, s2 = 0.f;
    for (int c = 0; c < 64; c++) { s += g_ps[c * Hz + f]; s2 += g_ps2[c * Hz + f]; }
    float mean = s * (1.f / 65536.f);
    float var  = s2 * (1.f / 65536.f) - mean * mean;
    float rstd = rsqrtf(var + 1e-5f);
    float a = rstd * scale[f];
    g_bnA[f] = a;
    g_bnB[f] = bias[f] - mean * a;
}

__global__ void bn_apply(float* __restrict__ h)
{
    int idx = blockIdx.x * 256 + threadIdx.x;      // grid 32768, float4 per thread
    float4 v = reinterpret_cast<float4*>(h)[idx];
    int f = (idx & 127) * 4;
    float4 a = *reinterpret_cast<const float4*>(&g_bnA[f]);
    float4 b = *reinterpret_cast<const float4*>(&g_bnB[f]);
    v.x = v.x * a.x + b.x;
    v.y = v.y * a.y + b.y;
    v.z = v.z * a.z + b.z;
    v.w = v.w * a.w + b.w;
    reinterpret_cast<float4*>(h)[idx] = v;
}

__global__ void head_kernel(const float* __restrict__ h2,
                            const float* __restrict__ Wd1, const float* __restrict__ bd1,
                            const float* __restrict__ Wd2, const float* __restrict__ bd2,
                            float* __restrict__ out)
{
    __shared__ float sh[512];
    __shared__ float sy[16];
    int b = blockIdx.x;
    int tid = threadIdx.x;      // 512 threads
    float v = h2[((size_t)b * 1024 + 1023) * Hz + tid];
    sh[tid] = v * g_bnA[tid] + g_bnB[tid];   // bn2 applied here (stats only)
    __syncthreads();

    int w = tid >> 5, lane = tid & 31;
    float s = 0.f;
    for (int f = lane; f < 512; f += 32) s += sh[f] * Wd1[f * 16 + w];
#pragma unroll
    for (int off = 16; off; off >>= 1) s += __shfl_down_sync(0xffffffffu, s, off);
    if (lane == 0) sy[w] = fmaxf(s + bd1[w], 0.f);
    __syncthreads();
    if (tid == 0) {
        float o = bd2[0];
#pragma unroll
        for (int j = 0; j < 16; j++) o += sy[j] * Wd2[j];
        out[b] = o;
    }
}

// ---------------------------------------------------------------------------
extern "C" void kernel_launch(void* const* d_in, const int* in_sizes, int n_in,
                              void* d_out, int out_size)
{
    const float* x    = (const float*)d_in[0];
    const float* Wx1  = (const float*)d_in[1];
    const float* Wh1  = (const float*)d_in[2];
    const float* b1   = (const float*)d_in[3];
    const float* s1   = (const float*)d_in[4];
    const float* bi1  = (const float*)d_in[5];
    const float* Wx2  = (const float*)d_in[6];
    const float* Wh2  = (const float*)d_in[7];
    const float* b2   = (const float*)d_in[8];
    const float* s2   = (const float*)d_in[9];
    const float* bi2  = (const float*)d_in[10];
    const float* Wd1  = (const float*)d_in[11];
    const float* bd1  = (const float*)d_in[12];
    const float* Wd2  = (const float*)d_in[13];
    const float* bd2  = (const float*)d_in[14];
    float* out = (float*)d_out;

    float *xg, *h1, *h2;
    cudaGetSymbolAddress((void**)&xg, g_xg);
    cudaGetSymbolAddress((void**)&h1, g_h1);
    cudaGetSymbolAddress((void**)&h2, g_h2);

    cudaFuncSetAttribute(lstm_rec, cudaFuncAttributeMaxDynamicSharedMemorySize, REC_SMEM);

    // layer 1
    sgemm_xg<<<dim3(16, 512), 256>>>(x, Wx1, b1, xg, Dz);
    reset_state<<<64, 512>>>();
    lstm_rec<<<128, 256, REC_SMEM>>>(Wh1, xg, h1);
    bn_partial<<<dim3(4, 64), 128>>>(h1);
    bn_finalize<<<4, 128>>>(s1, bi1);
    bn_apply<<<32768, 256>>>(h1);

    // layer 2
    sgemm_xg<<<dim3(16, 512), 256>>>(h1, Wx2, b2, xg, Hz);
    reset_state<<<64, 512>>>();
    lstm_rec<<<128, 256, REC_SMEM>>>(Wh2, xg, h2);
    bn_partial<<<dim3(4, 64), 128>>>(h2);
    bn_finalize<<<4, 128>>>(s2, bi2);

    // head (applies bn2 to last timestep only)
    head_kernel<<<64, 512>>>(h2, Wd1, bd1, Wd2, bd2, out);
}